// round 12
// baseline (speedup 1.0000x reference)
#include <cuda_runtime.h>
#include <math.h>
#include <stdint.h>

#define BB 4
#define NN 4096
#define FF 512
#define HA 128
#define HV 32

// Scratch (device globals: no allocation allowed)
// g_hn stores normalized h with PERMUTED k within each 32-chunk:
//   newcol = (chunk*32) + (k%4)*8 + (k/4)%8
__device__ float g_hn[BB][NN][HA];
__device__ float g_part[BB][32];

// ---------------------------------------------------------------------------
__device__ __forceinline__ float tf32r(float x) {
    uint32_t o;
    asm("cvt.rna.tf32.f32 %0, %1;" : "=r"(o) : "f"(x));
    return __uint_as_float(o);
}

__device__ __forceinline__ uint32_t s2u(const void* p) {
    uint32_t a;
    asm("{ .reg .u64 t; cvta.to.shared.u64 t, %1; cvt.u32.u64 %0, t; }"
        : "=r"(a) : "l"(p));
    return a;
}

__device__ __forceinline__ void cp16(uint32_t dst, const float* src) {
    asm volatile("cp.async.cg.shared.global [%0], [%1], 16;"
                 :: "r"(dst), "l"(src));
}

__device__ __forceinline__ void mma_tf32(float* d, const uint32_t* a,
                                         const uint32_t* b) {
    asm volatile(
        "mma.sync.aligned.m16n8k8.row.col.f32.tf32.tf32.f32 "
        "{%0,%1,%2,%3}, {%4,%5,%6,%7}, {%8,%9}, {%0,%1,%2,%3};"
        : "+f"(d[0]), "+f"(d[1]), "+f"(d[2]), "+f"(d[3])
        : "r"(a[0]), "r"(a[1]), "r"(a[2]), "r"(a[3]), "r"(b[0]), "r"(b[1]));
}

// mov-free variant: every operand is an individual scalar expression
__device__ __forceinline__ void mma4(float* d,
                                     float a0, float a1, float a2, float a3,
                                     float b0, float b1) {
    asm volatile(
        "mma.sync.aligned.m16n8k8.row.col.f32.tf32.tf32.f32 "
        "{%0,%1,%2,%3}, {%4,%5,%6,%7}, {%8,%9}, {%0,%1,%2,%3};"
        : "+f"(d[0]), "+f"(d[1]), "+f"(d[2]), "+f"(d[3])
        : "r"(__float_as_uint(a0)), "r"(__float_as_uint(a1)),
          "r"(__float_as_uint(a2)), "r"(__float_as_uint(a3)),
          "r"(__float_as_uint(b0)), "r"(__float_as_uint(b1)));
}

__device__ __forceinline__ int kperm(int col) {
    // permute k within its 32-chunk: (k%4)*8 + (k/4)%8
    return (col & ~31) | ((col & 3) << 3) | ((col & 31) >> 2);
}

// ---------------------------------------------------------------------------
// FUSED hc kernel, 3-stage cp.async pipeline. Epilogue writes g_hn with the
// k-permutation applied in the staging STS.
// ---------------------------------------------------------------------------
#define STAGE_W 10240
#define AS_OFF 0             // As: [128][36] = 4608
#define BS_OFF 4608          // Bs: [32][136] = 4352
#define WS_OFF 8960          // Ws: [32][40]  = 1280
#define REDO 30720           // [128][8]
#define RINVO 31744          // [128]
#define CREDO 31872          // [128]
#define CWO 32000            // [4]
#define HC_FLOATS 32004
#define HC_SMEM_BYTES (HC_FLOATS * 4)

__global__ __launch_bounds__(256, 1) void hc_kernel(const float* __restrict__ obs,
                                                    const float* __restrict__ gen_number,
                                                    const float* __restrict__ W_gen,
                                                    const float* __restrict__ b_gen,
                                                    const float* __restrict__ W_act,
                                                    const float* __restrict__ b_act,
                                                    const float* __restrict__ W_v1,
                                                    const float* __restrict__ b_v1,
                                                    const float* __restrict__ W_v2,
                                                    const float* __restrict__ b_v2) {
    extern __shared__ float sm[];
    const uint32_t smb = s2u(sm);

    const int b  = blockIdx.y;
    const int m0 = blockIdx.x * 128;
    const int tid = threadIdx.x;
    const int wid = tid >> 5;
    const int lane = tid & 31;
    const int g = lane >> 2;
    const int t = lane & 3;
    const int wm = wid >> 1;
    const int wn = wid & 1;

    const float* obs_b = obs + ((size_t)b * NN + m0) * FF;

    float acc[2][8][4];
    float accv[2][4][4];
#pragma unroll
    for (int mi = 0; mi < 2; mi++) {
#pragma unroll
        for (int ni = 0; ni < 8; ni++)
#pragma unroll
            for (int q = 0; q < 4; q++) acc[mi][ni][q] = 0.f;
#pragma unroll
        for (int ni = 0; ni < 4; ni++)
#pragma unroll
            for (int q = 0; q < 4; q++) accv[mi][ni][q] = 0.f;
    }

    auto issue = [&](int ck, int s) {
        const int k0 = ck * 32;
        uint32_t as = smb + (uint32_t)((s * STAGE_W + AS_OFF) * 4);
        uint32_t bs = smb + (uint32_t)((s * STAGE_W + BS_OFF) * 4);
        uint32_t ws = smb + (uint32_t)((s * STAGE_W + WS_OFF) * 4);
#pragma unroll
        for (int i = 0; i < 4; i++) {
            int c = tid + i * 256;
            int row = c >> 3, kc = c & 7;
            cp16(as + (uint32_t)(row * 36 + kc * 4) * 4u,
                 obs_b + (size_t)row * FF + k0 + kc * 4);
        }
#pragma unroll
        for (int i = 0; i < 4; i++) {
            int c = tid + i * 256;
            int kk = c >> 5, cg = c & 31;
            cp16(bs + (uint32_t)(kk * 136 + cg * 4) * 4u,
                 W_act + (size_t)(k0 + kk) * HA + cg * 4);
        }
        {
            int kk = tid >> 3, cg = tid & 7;
            cp16(ws + (uint32_t)(kk * 40 + cg * 4) * 4u,
                 W_v1 + (size_t)(k0 + kk) * HV + cg * 4);
        }
    };

    issue(0, 0);
    asm volatile("cp.async.commit_group;" ::: "memory");
    issue(1, 1);
    asm volatile("cp.async.commit_group;" ::: "memory");
    issue(2, 2);
    asm volatile("cp.async.commit_group;" ::: "memory");
    asm volatile("cp.async.wait_group 2;" ::: "memory");
    __syncthreads();

#pragma unroll 1
    for (int ck = 0; ck < 16; ck++) {
        const int s = ck % 3;
        const float* A  = sm + s * STAGE_W + AS_OFF + wm * 32 * 36;
        const float* Bm = sm + s * STAGE_W + BS_OFF + wn * 64;
        const float* Wc = sm + s * STAGE_W + WS_OFF;
#pragma unroll
        for (int ks = 0; ks < 4; ks++) {
            const int kk = ks * 8;
            uint32_t af[2][4];
#pragma unroll
            for (int mi = 0; mi < 2; mi++) {
                const float* ap = A + (mi * 16 + g) * 36 + kk + t;
                af[mi][0] = __float_as_uint(ap[0]);
                af[mi][1] = __float_as_uint(ap[8 * 36]);
                af[mi][2] = __float_as_uint(ap[4]);
                af[mi][3] = __float_as_uint(ap[8 * 36 + 4]);
            }
            uint32_t bf[8][2];
#pragma unroll
            for (int ni = 0; ni < 8; ni++) {
                const float* bp = Bm + (kk + t) * 136 + ni * 8 + g;
                bf[ni][0] = __float_as_uint(bp[0]);
                bf[ni][1] = __float_as_uint(bp[4 * 136]);
            }
#pragma unroll
            for (int mi = 0; mi < 2; mi++)
#pragma unroll
                for (int ni = 0; ni < 8; ni++)
                    mma_tf32(acc[mi][ni], af[mi], bf[ni]);
            if (wn == 0) {
                uint32_t bc[4][2];
#pragma unroll
                for (int ni = 0; ni < 4; ni++) {
                    const float* bp = Wc + (kk + t) * 40 + ni * 8 + g;
                    bc[ni][0] = __float_as_uint(bp[0]);
                    bc[ni][1] = __float_as_uint(bp[4 * 40]);
                }
#pragma unroll
                for (int mi = 0; mi < 2; mi++)
#pragma unroll
                    for (int ni = 0; ni < 4; ni++)
                        mma_tf32(accv[mi][ni], af[mi], bc[ni]);
            }
        }
        __syncthreads();
        if (ck + 3 < 16) issue(ck + 3, s);
        asm volatile("cp.async.commit_group;" ::: "memory");
        if (ck < 15) {
            asm volatile("cp.async.wait_group 2;" ::: "memory");
            __syncthreads();
        }
    }

    float gv;
    {
        float x = gen_number[b] * W_gen[0] + b_gen[0];
        gv = (x > 0.f) ? x : 0.01f * x;
    }

#pragma unroll
    for (int ni = 0; ni < 8; ni++) {
        int c0 = wn * 64 + ni * 8 + 2 * t;
        float a0 = fmaf(gv, W_act[(size_t)FF * HA + c0], b_act[c0]);
        float a1 = fmaf(gv, W_act[(size_t)FF * HA + c0 + 1], b_act[c0 + 1]);
#pragma unroll
        for (int mi = 0; mi < 2; mi++) {
            acc[mi][ni][0] += a0; acc[mi][ni][1] += a1;
            acc[mi][ni][2] += a0; acc[mi][ni][3] += a1;
        }
    }

    float* RED = sm + REDO;
#pragma unroll
    for (int mi = 0; mi < 2; mi++)
#pragma unroll
        for (int d = 0; d < 2; d++) {
            float s = 0.f;
#pragma unroll
            for (int ni = 0; ni < 8; ni++) {
                s = fmaf(acc[mi][ni][2 * d], acc[mi][ni][2 * d], s);
                s = fmaf(acc[mi][ni][2 * d + 1], acc[mi][ni][2 * d + 1], s);
            }
            int row = wm * 32 + mi * 16 + g + 8 * d;
            RED[row * 8 + wn * 4 + t] = s;
        }
    __syncthreads();
    float* RINV = sm + RINVO;
    if (tid < 128) {
        float s = 0.f;
#pragma unroll
        for (int x = 0; x < 8; x++) s += RED[tid * 8 + x];
        RINV[tid] = 1.f / fmaxf(sqrtf(s), 1e-8f);
    }
    __syncthreads();

    // normalize + tf32 round -> stage with k-permutation applied
    float* STG = sm;
#pragma unroll
    for (int mi = 0; mi < 2; mi++)
#pragma unroll
        for (int d = 0; d < 2; d++) {
            int row = wm * 32 + mi * 16 + g + 8 * d;
            float iv = RINV[row];
#pragma unroll
            for (int ni = 0; ni < 8; ni++) {
                int col = wn * 64 + ni * 8 + 2 * t;
                STG[row * 132 + kperm(col)]     = tf32r(acc[mi][ni][2 * d] * iv);
                STG[row * 132 + kperm(col + 1)] = tf32r(acc[mi][ni][2 * d + 1] * iv);
            }
        }

    float* CRED = sm + CREDO;
    if (wn == 0) {
#pragma unroll
        for (int mi = 0; mi < 2; mi++)
#pragma unroll
            for (int d = 0; d < 2; d++) {
                float cv = 0.f;
#pragma unroll
                for (int ni = 0; ni < 4; ni++) {
#pragma unroll
                    for (int j = 0; j < 2; j++) {
                        int cc = ni * 8 + 2 * t + j;
                        float hvv = accv[mi][ni][2 * d + j] +
                                    fmaf(gv, W_v1[(size_t)FF * HV + cc], b_v1[cc]);
                        hvv = fmaxf(hvv, 0.f);
                        cv = fmaf(hvv, W_v2[cc], cv);
                    }
                }
                cv += __shfl_xor_sync(0xffffffffu, cv, 1);
                cv += __shfl_xor_sync(0xffffffffu, cv, 2);
                if (t == 0) {
                    int row = wm * 32 + mi * 16 + g + 8 * d;
                    CRED[row] = cv + b_v2[0];
                }
            }
    }
    __syncthreads();

#pragma unroll
    for (int i = 0; i < 16; i++) {
        int idx = tid + i * 256;
        int row = idx >> 5, c4 = idx & 31;
        float4 v = *(float4*)&STG[row * 132 + c4 * 4];
        *(float4*)&g_hn[b][m0 + row][c4 * 4] = v;
    }

    float* CW = sm + CWO;
    if (tid < 128) {
        float v = CRED[tid];
#pragma unroll
        for (int off = 16; off > 0; off >>= 1)
            v += __shfl_down_sync(0xffffffffu, v, off);
        if ((tid & 31) == 0) CW[tid >> 5] = v;
    }
    __syncthreads();
    if (tid == 0)
        g_part[b][blockIdx.x] = CW[0] + CW[1] + CW[2] + CW[3];
}

// ---------------------------------------------------------------------------
// Actor v8: as R11 (128x128, 2 CTAs/SM, 3-stage cp.async, proven store
// scheme) but fragment loads are LDS.128 over the k-permuted layout, with
// MOV-FREE operand passing (each mma operand is an individual scalar).
// 24 LDS.128 per thread-chunk instead of 96 LDS.32.
// ---------------------------------------------------------------------------
#define CBUF 4608
#define ACT_WORDS (6 * CBUF)             // 27648
#define ACT_SMEM_BYTES (ACT_WORDS * 4)   // 110592
#define LDT 132                          // mirror staging stride

__global__ __launch_bounds__(256, 2) void actor_kernel(float* __restrict__ out,
                                                       int out_size) {
    extern __shared__ float smem[];
    const uint32_t smb = s2u(smem);

    const int tid = threadIdx.x;
    const int wid = tid >> 5;
    const int lane = tid & 31;
    const int g = lane >> 2;
    const int t = lane & 3;
    const int wm = wid >> 2;             // 0..1
    const int wn = wid & 3;              // 0..3
    const int b = blockIdx.y;
    const int cid = blockIdx.x;

    // fold critic finalize into one CTA
    if (cid == 0 && b == 0 && tid < BB) {
        float s = 0.f;
#pragma unroll
        for (int k = 0; k < 32; k++) s += g_part[tid][k];
        out[(size_t)out_size - BB + tid] = s * (1.f / NN);
    }

    // decode cid -> (i, j), j >= i, 528 per batch
    int i = 0, j;
    {
        int c = cid, ch;
        while (c >= (ch = 32 - i)) { c -= ch; i++; }
        j = i + c;
    }

    const float* aSrc = &g_hn[b][i * 128][0];
    const float* bSrc = &g_hn[b][j * 128][0];

    // chunk loader: chunk ck (32 permuted k-values) of A and B into stage s
    auto issue = [&](int ck, int s) {
        const int k0 = ck * 32;
        uint32_t as = smb + (uint32_t)(s * CBUF * 4);
        uint32_t bs = smb + (uint32_t)((3 + s) * CBUF * 4);
#pragma unroll
        for (int it = 0; it < 4; it++) {
            int c = tid + it * 256;
            int row = c >> 3, kc = c & 7;
            cp16(as + (uint32_t)(row * 36 + kc * 4) * 4u,
                 aSrc + (size_t)row * HA + k0 + kc * 4);
        }
#pragma unroll
        for (int it = 0; it < 4; it++) {
            int c = tid + it * 256;
            int row = c >> 3, kc = c & 7;
            cp16(bs + (uint32_t)(row * 36 + kc * 4) * 4u,
                 bSrc + (size_t)row * HA + k0 + kc * 4);
        }
        asm volatile("cp.async.commit_group;" ::: "memory");
    };

    float acc[4][4][4];
#pragma unroll
    for (int mi = 0; mi < 4; mi++)
#pragma unroll
        for (int ni = 0; ni < 4; ni++)
#pragma unroll
            for (int q = 0; q < 4; q++) acc[mi][ni][q] = 0.f;

    // compute one chunk from stage s: LDS.128 fragments, mov-free mma feed
    auto compute = [&](int s) {
        const float* A  = smem + s * CBUF + (wm * 64 + g) * 36 + t * 8;
        const float* Bm = smem + (3 + s) * CBUF + (wn * 32 + g) * 36 + t * 8;
#pragma unroll
        for (int kp = 0; kp < 2; kp++) {
            float4 bv0 = *(const float4*)(Bm + 0 * 288 + kp * 4);
            float4 bv1 = *(const float4*)(Bm + 1 * 288 + kp * 4);
            float4 bv2 = *(const float4*)(Bm + 2 * 288 + kp * 4);
            float4 bv3 = *(const float4*)(Bm + 3 * 288 + kp * 4);
#pragma unroll
            for (int mi = 0; mi < 4; mi++) {
                float4 x = *(const float4*)(A + mi * 576 + kp * 4);
                float4 y = *(const float4*)(A + mi * 576 + 288 + kp * 4);
                // kstep 2kp
                mma4(acc[mi][0], x.x, y.x, x.y, y.y, bv0.x, bv0.y);
                mma4(acc[mi][1], x.x, y.x, x.y, y.y, bv1.x, bv1.y);
                mma4(acc[mi][2], x.x, y.x, x.y, y.y, bv2.x, bv2.y);
                mma4(acc[mi][3], x.x, y.x, x.y, y.y, bv3.x, bv3.y);
                // kstep 2kp+1
                mma4(acc[mi][0], x.z, y.z, x.w, y.w, bv0.z, bv0.w);
                mma4(acc[mi][1], x.z, y.z, x.w, y.w, bv1.z, bv1.w);
                mma4(acc[mi][2], x.z, y.z, x.w, y.w, bv2.z, bv2.w);
                mma4(acc[mi][3], x.z, y.z, x.w, y.w, bv3.z, bv3.w);
            }
        }
    };

    // 3-deep prologue: chunks 0,1,2 in flight before first compute
    issue(0, 0);
    issue(1, 1);
    issue(2, 2);
    asm volatile("cp.async.wait_group 2;" ::: "memory");   // chunk 0 ready
    __syncthreads();

    compute(0);
    __syncthreads();                                       // stage 0 free
    issue(3, 0);
    asm volatile("cp.async.wait_group 2;" ::: "memory");   // chunk 1 ready
    __syncthreads();

    compute(1);
    asm volatile("cp.async.wait_group 1;" ::: "memory");   // chunk 2 ready
    __syncthreads();

    compute(2);
    asm volatile("cp.async.wait_group 0;" ::: "memory");   // chunk 3 ready
    __syncthreads();

    compute(0);                                            // chunk 3 in stage 0

    // direct store: tile (i, j), coalesced float2 from registers
    {
        size_t rbase = ((size_t)b * NN + i * 128 + wm * 64 + g) * NN +
                       (size_t)j * 128 + wn * 32 + 2 * t;
#pragma unroll
        for (int mi = 0; mi < 4; mi++) {
            size_t r0 = rbase + (size_t)(mi * 16) * NN;
#pragma unroll
            for (int ni = 0; ni < 4; ni++) {
                float2 v0 = make_float2(-acc[mi][ni][0], -acc[mi][ni][1]);
                float2 v1 = make_float2(-acc[mi][ni][2], -acc[mi][ni][3]);
                *(float2*)(out + r0 + ni * 8) = v0;
                *(float2*)(out + r0 + (size_t)8 * NN + ni * 8) = v1;
            }
        }
    }

    if (j > i) {
        __syncthreads();      // everyone done reading stage buffers
        // stage transposed tile into the (now free) buffers: [col][row]
        float* STGb = smem;
        const int cbase = wn * 32 + 2 * t;
        const int rb = wm * 64 + g;
#pragma unroll
        for (int mi = 0; mi < 4; mi++) {
            int r = rb + mi * 16;
#pragma unroll
            for (int ni = 0; ni < 4; ni++) {
                int c = cbase + ni * 8;
                STGb[c * LDT + r]           = -acc[mi][ni][0];
                STGb[(c + 1) * LDT + r]     = -acc[mi][ni][1];
                STGb[c * LDT + r + 8]       = -acc[mi][ni][2];
                STGb[(c + 1) * LDT + r + 8] = -acc[mi][ni][3];
            }
        }
        __syncthreads();
        // mirrored store: tile (j, i), coalesced
        size_t tbase = ((size_t)b * NN + (size_t)j * 128) * NN + (size_t)i * 128;
#pragma unroll
        for (int it = 0; it < 16; it++) {
            int idx = tid + it * 256;
            int c = idx >> 5, q4 = idx & 31;
            float4 v = *(float4*)&STGb[c * LDT + q4 * 4];
            *(float4*)(out + tbase + (size_t)c * NN + q4 * 4) = v;
        }
    }
}

// ---------------------------------------------------------------------------
extern "C" void kernel_launch(void* const* d_in, const int* in_sizes, int n_in,
                              void* d_out, int out_size) {
    const float* obs        = (const float*)d_in[0];
    const float* gen_number = (const float*)d_in[1];
    const float* W_gen      = (const float*)d_in[2];
    const float* b_gen      = (const float*)d_in[3];
    const float* W_act      = (const float*)d_in[4];
    const float* b_act      = (const float*)d_in[5];
    const float* W_v1       = (const float*)d_in[6];
    const float* b_v1       = (const float*)d_in[7];
    const float* W_v2       = (const float*)d_in[8];
    const float* b_v2       = (const float*)d_in[9];
    float* out = (float*)d_out;

    cudaFuncSetAttribute(hc_kernel, cudaFuncAttributeMaxDynamicSharedMemorySize,
                         HC_SMEM_BYTES);
    cudaFuncSetAttribute(actor_kernel, cudaFuncAttributeMaxDynamicSharedMemorySize,
                         ACT_SMEM_BYTES);

    hc_kernel<<<dim3(NN / 128, BB), 256, HC_SMEM_BYTES>>>(
        obs, gen_number, W_gen, b_gen, W_act, b_act, W_v1, b_v1, W_v2, b_v2);
    actor_kernel<<<dim3(528, BB), 256, ACT_SMEM_BYTES>>>(out, out_size);
}

// round 15
// speedup vs baseline: 1.1280x; 1.1280x over previous
#include <cuda_runtime.h>
#include <math.h>
#include <stdint.h>

#define BB 4
#define NN 4096
#define FF 512
#define HA 128
#define HV 32

// Scratch (device globals: no allocation allowed)
__device__ float g_hn[BB][NN][HA];    // normalized h, row-major, tf32-rounded (8 MB)
__device__ float g_part[BB][32];

// ---------------------------------------------------------------------------
__device__ __forceinline__ float tf32r(float x) {
    uint32_t o;
    asm("cvt.rna.tf32.f32 %0, %1;" : "=r"(o) : "f"(x));
    return __uint_as_float(o);
}

__device__ __forceinline__ uint32_t s2u(const void* p) {
    uint32_t a;
    asm("{ .reg .u64 t; cvta.to.shared.u64 t, %1; cvt.u32.u64 %0, t; }"
        : "=r"(a) : "l"(p));
    return a;
}

__device__ __forceinline__ void cp16(uint32_t dst, const float* src) {
    asm volatile("cp.async.cg.shared.global [%0], [%1], 16;"
                 :: "r"(dst), "l"(src));
}

__device__ __forceinline__ void mma_tf32(float* d, const uint32_t* a,
                                         const uint32_t* b) {
    asm volatile(
        "mma.sync.aligned.m16n8k8.row.col.f32.tf32.tf32.f32 "
        "{%0,%1,%2,%3}, {%4,%5,%6,%7}, {%8,%9}, {%0,%1,%2,%3};"
        : "+f"(d[0]), "+f"(d[1]), "+f"(d[2]), "+f"(d[3])
        : "r"(a[0]), "r"(a[1]), "r"(a[2]), "r"(a[3]), "r"(b[0]), "r"(b[1]));
}

// ---------------------------------------------------------------------------
// FUSED hc kernel, 3-stage cp.async pipeline (R11 version, plain layout).
// ---------------------------------------------------------------------------
#define STAGE_W 10240
#define AS_OFF 0             // As: [128][36] = 4608
#define BS_OFF 4608          // Bs: [32][136] = 4352
#define WS_OFF 8960          // Ws: [32][40]  = 1280
#define REDO 30720           // [128][8]
#define RINVO 31744          // [128]
#define CREDO 31872          // [128]
#define CWO 32000            // [4]
#define HC_FLOATS 32004
#define HC_SMEM_BYTES (HC_FLOATS * 4)

__global__ __launch_bounds__(256, 1) void hc_kernel(const float* __restrict__ obs,
                                                    const float* __restrict__ gen_number,
                                                    const float* __restrict__ W_gen,
                                                    const float* __restrict__ b_gen,
                                                    const float* __restrict__ W_act,
                                                    const float* __restrict__ b_act,
                                                    const float* __restrict__ W_v1,
                                                    const float* __restrict__ b_v1,
                                                    const float* __restrict__ W_v2,
                                                    const float* __restrict__ b_v2) {
    extern __shared__ float sm[];
    const uint32_t smb = s2u(sm);

    const int b  = blockIdx.y;
    const int m0 = blockIdx.x * 128;
    const int tid = threadIdx.x;
    const int wid = tid >> 5;
    const int lane = tid & 31;
    const int g = lane >> 2;
    const int t = lane & 3;
    const int wm = wid >> 1;
    const int wn = wid & 1;

    const float* obs_b = obs + ((size_t)b * NN + m0) * FF;

    float acc[2][8][4];
    float accv[2][4][4];
#pragma unroll
    for (int mi = 0; mi < 2; mi++) {
#pragma unroll
        for (int ni = 0; ni < 8; ni++)
#pragma unroll
            for (int q = 0; q < 4; q++) acc[mi][ni][q] = 0.f;
#pragma unroll
        for (int ni = 0; ni < 4; ni++)
#pragma unroll
            for (int q = 0; q < 4; q++) accv[mi][ni][q] = 0.f;
    }

    auto issue = [&](int ck, int s) {
        const int k0 = ck * 32;
        uint32_t as = smb + (uint32_t)((s * STAGE_W + AS_OFF) * 4);
        uint32_t bs = smb + (uint32_t)((s * STAGE_W + BS_OFF) * 4);
        uint32_t ws = smb + (uint32_t)((s * STAGE_W + WS_OFF) * 4);
#pragma unroll
        for (int i = 0; i < 4; i++) {
            int c = tid + i * 256;
            int row = c >> 3, kc = c & 7;
            cp16(as + (uint32_t)(row * 36 + kc * 4) * 4u,
                 obs_b + (size_t)row * FF + k0 + kc * 4);
        }
#pragma unroll
        for (int i = 0; i < 4; i++) {
            int c = tid + i * 256;
            int kk = c >> 5, cg = c & 31;
            cp16(bs + (uint32_t)(kk * 136 + cg * 4) * 4u,
                 W_act + (size_t)(k0 + kk) * HA + cg * 4);
        }
        {
            int kk = tid >> 3, cg = tid & 7;
            cp16(ws + (uint32_t)(kk * 40 + cg * 4) * 4u,
                 W_v1 + (size_t)(k0 + kk) * HV + cg * 4);
        }
    };

    issue(0, 0);
    asm volatile("cp.async.commit_group;" ::: "memory");
    issue(1, 1);
    asm volatile("cp.async.commit_group;" ::: "memory");
    issue(2, 2);
    asm volatile("cp.async.commit_group;" ::: "memory");
    asm volatile("cp.async.wait_group 2;" ::: "memory");
    __syncthreads();

#pragma unroll 1
    for (int ck = 0; ck < 16; ck++) {
        const int s = ck % 3;
        const float* A  = sm + s * STAGE_W + AS_OFF + wm * 32 * 36;
        const float* Bm = sm + s * STAGE_W + BS_OFF + wn * 64;
        const float* Wc = sm + s * STAGE_W + WS_OFF;
#pragma unroll
        for (int ks = 0; ks < 4; ks++) {
            const int kk = ks * 8;
            uint32_t af[2][4];
#pragma unroll
            for (int mi = 0; mi < 2; mi++) {
                const float* ap = A + (mi * 16 + g) * 36 + kk + t;
                af[mi][0] = __float_as_uint(ap[0]);
                af[mi][1] = __float_as_uint(ap[8 * 36]);
                af[mi][2] = __float_as_uint(ap[4]);
                af[mi][3] = __float_as_uint(ap[8 * 36 + 4]);
            }
            uint32_t bf[8][2];
#pragma unroll
            for (int ni = 0; ni < 8; ni++) {
                const float* bp = Bm + (kk + t) * 136 + ni * 8 + g;
                bf[ni][0] = __float_as_uint(bp[0]);
                bf[ni][1] = __float_as_uint(bp[4 * 136]);
            }
#pragma unroll
            for (int mi = 0; mi < 2; mi++)
#pragma unroll
                for (int ni = 0; ni < 8; ni++)
                    mma_tf32(acc[mi][ni], af[mi], bf[ni]);
            if (wn == 0) {
                uint32_t bc[4][2];
#pragma unroll
                for (int ni = 0; ni < 4; ni++) {
                    const float* bp = Wc + (kk + t) * 40 + ni * 8 + g;
                    bc[ni][0] = __float_as_uint(bp[0]);
                    bc[ni][1] = __float_as_uint(bp[4 * 40]);
                }
#pragma unroll
                for (int mi = 0; mi < 2; mi++)
#pragma unroll
                    for (int ni = 0; ni < 4; ni++)
                        mma_tf32(accv[mi][ni], af[mi], bc[ni]);
            }
        }
        __syncthreads();
        if (ck + 3 < 16) issue(ck + 3, s);
        asm volatile("cp.async.commit_group;" ::: "memory");
        if (ck < 15) {
            asm volatile("cp.async.wait_group 2;" ::: "memory");
            __syncthreads();
        }
    }

    float gv;
    {
        float x = gen_number[b] * W_gen[0] + b_gen[0];
        gv = (x > 0.f) ? x : 0.01f * x;
    }

#pragma unroll
    for (int ni = 0; ni < 8; ni++) {
        int c0 = wn * 64 + ni * 8 + 2 * t;
        float a0 = fmaf(gv, W_act[(size_t)FF * HA + c0], b_act[c0]);
        float a1 = fmaf(gv, W_act[(size_t)FF * HA + c0 + 1], b_act[c0 + 1]);
#pragma unroll
        for (int mi = 0; mi < 2; mi++) {
            acc[mi][ni][0] += a0; acc[mi][ni][1] += a1;
            acc[mi][ni][2] += a0; acc[mi][ni][3] += a1;
        }
    }

    float* RED = sm + REDO;
#pragma unroll
    for (int mi = 0; mi < 2; mi++)
#pragma unroll
        for (int d = 0; d < 2; d++) {
            float s = 0.f;
#pragma unroll
            for (int ni = 0; ni < 8; ni++) {
                s = fmaf(acc[mi][ni][2 * d], acc[mi][ni][2 * d], s);
                s = fmaf(acc[mi][ni][2 * d + 1], acc[mi][ni][2 * d + 1], s);
            }
            int row = wm * 32 + mi * 16 + g + 8 * d;
            RED[row * 8 + wn * 4 + t] = s;
        }
    __syncthreads();
    float* RINV = sm + RINVO;
    if (tid < 128) {
        float s = 0.f;
#pragma unroll
        for (int x = 0; x < 8; x++) s += RED[tid * 8 + x];
        RINV[tid] = 1.f / fmaxf(sqrtf(s), 1e-8f);
    }
    __syncthreads();

    float* STG = sm;
#pragma unroll
    for (int mi = 0; mi < 2; mi++)
#pragma unroll
        for (int d = 0; d < 2; d++) {
            int row = wm * 32 + mi * 16 + g + 8 * d;
            float iv = RINV[row];
#pragma unroll
            for (int ni = 0; ni < 8; ni++) {
                int col = wn * 64 + ni * 8 + 2 * t;
                STG[row * 132 + col]     = tf32r(acc[mi][ni][2 * d] * iv);
                STG[row * 132 + col + 1] = tf32r(acc[mi][ni][2 * d + 1] * iv);
            }
        }

    float* CRED = sm + CREDO;
    if (wn == 0) {
#pragma unroll
        for (int mi = 0; mi < 2; mi++)
#pragma unroll
            for (int d = 0; d < 2; d++) {
                float cv = 0.f;
#pragma unroll
                for (int ni = 0; ni < 4; ni++) {
#pragma unroll
                    for (int j = 0; j < 2; j++) {
                        int cc = ni * 8 + 2 * t + j;
                        float hvv = accv[mi][ni][2 * d + j] +
                                    fmaf(gv, W_v1[(size_t)FF * HV + cc], b_v1[cc]);
                        hvv = fmaxf(hvv, 0.f);
                        cv = fmaf(hvv, W_v2[cc], cv);
                    }
                }
                cv += __shfl_xor_sync(0xffffffffu, cv, 1);
                cv += __shfl_xor_sync(0xffffffffu, cv, 2);
                if (t == 0) {
                    int row = wm * 32 + mi * 16 + g + 8 * d;
                    CRED[row] = cv + b_v2[0];
                }
            }
    }
    __syncthreads();

#pragma unroll
    for (int i = 0; i < 16; i++) {
        int idx = tid + i * 256;
        int row = idx >> 5, c4 = idx & 31;
        float4 v = *(float4*)&STG[row * 132 + c4 * 4];
        *(float4*)&g_hn[b][m0 + row][c4 * 4] = v;
    }

    float* CW = sm + CWO;
    if (tid < 128) {
        float v = CRED[tid];
#pragma unroll
        for (int off = 16; off > 0; off >>= 1)
            v += __shfl_down_sync(0xffffffffu, v, off);
        if ((tid & 31) == 0) CW[tid >> 5] = v;
    }
    __syncthreads();
    if (tid == 0)
        g_part[b][blockIdx.x] = CW[0] + CW[1] + CW[2] + CW[3];
}

// ---------------------------------------------------------------------------
// Actor v9: 128 threads, warp grid 2x2, warp tile 64x64 (halved cross-warp
// smem read redundancy vs 2x4/64x32). 128x128 CTA tile, 3-stage cp.async,
// 2 CTAs/SM (launch_bounds(128,2) -> 256-reg budget). Scalar-LDS fragments
// feed mma registers directly (proven). Symmetric j>=i + staged mirror.
// ---------------------------------------------------------------------------
#define CBUF 4608
#define ACT_WORDS (6 * CBUF)             // 27648
#define ACT_SMEM_BYTES (ACT_WORDS * 4)   // 110592
#define LDT 132                          // mirror staging stride

__global__ __launch_bounds__(128, 2) void actor_kernel(float* __restrict__ out,
                                                       int out_size) {
    extern __shared__ float smem[];
    const uint32_t smb = s2u(smem);

    const int tid = threadIdx.x;
    const int wid = tid >> 5;            // 0..3
    const int lane = tid & 31;
    const int g = lane >> 2;
    const int t = lane & 3;
    const int wm = wid >> 1;             // 0..1
    const int wn = wid & 1;              // 0..1
    const int b = blockIdx.y;
    const int cid = blockIdx.x;

    // fold critic finalize into one CTA
    if (cid == 0 && b == 0 && tid < BB) {
        float s = 0.f;
#pragma unroll
        for (int k = 0; k < 32; k++) s += g_part[tid][k];
        out[(size_t)out_size - BB + tid] = s * (1.f / NN);
    }

    // decode cid -> (i, j), j >= i, 528 per batch
    int i = 0, j;
    {
        int c = cid, ch;
        while (c >= (ch = 32 - i)) { c -= ch; i++; }
        j = i + c;
    }

    const float* aSrc = &g_hn[b][i * 128][0];
    const float* bSrc = &g_hn[b][j * 128][0];

    // chunk loader: chunk ck (32 k-values) of A and B into stage s
    auto issue = [&](int ck, int s) {
        const int k0 = ck * 32;
        uint32_t as = smb + (uint32_t)(s * CBUF * 4);
        uint32_t bs = smb + (uint32_t)((3 + s) * CBUF * 4);
#pragma unroll
        for (int it = 0; it < 8; it++) {
            int c = tid + it * 128;
            int row = c >> 3, kc = c & 7;
            cp16(as + (uint32_t)(row * 36 + kc * 4) * 4u,
                 aSrc + (size_t)row * HA + k0 + kc * 4);
        }
#pragma unroll
        for (int it = 0; it < 8; it++) {
            int c = tid + it * 128;
            int row = c >> 3, kc = c & 7;
            cp16(bs + (uint32_t)(row * 36 + kc * 4) * 4u,
                 bSrc + (size_t)row * HA + k0 + kc * 4);
        }
        asm volatile("cp.async.commit_group;" ::: "memory");
    };

    float acc[4][8][4];
#pragma unroll
    for (int mi = 0; mi < 4; mi++)
#pragma unroll
        for (int ni = 0; ni < 8; ni++)
#pragma unroll
            for (int q = 0; q < 4; q++) acc[mi][ni][q] = 0.f;

    // compute one chunk from stage s: 64x64 warp tile, scalar-LDS fragments
    auto compute = [&](int s) {
        const float* A  = smem + s * CBUF + (wm * 64) * 36;
        const float* Bm = smem + (3 + s) * CBUF + (wn * 64) * 36;
#pragma unroll
        for (int ks = 0; ks < 4; ks++) {
            const int kk = ks * 8;
            uint32_t af[4][4];
#pragma unroll
            for (int mi = 0; mi < 4; mi++) {
                const float* ap = A + (mi * 16 + g) * 36 + kk + t;
                af[mi][0] = __float_as_uint(ap[0]);
                af[mi][1] = __float_as_uint(ap[8 * 36]);
                af[mi][2] = __float_as_uint(ap[4]);
                af[mi][3] = __float_as_uint(ap[8 * 36 + 4]);
            }
            uint32_t bf[8][2];
#pragma unroll
            for (int ni = 0; ni < 8; ni++) {
                const float* bp = Bm + (ni * 8 + g) * 36 + kk + t;
                bf[ni][0] = __float_as_uint(bp[0]);
                bf[ni][1] = __float_as_uint(bp[4]);
            }
#pragma unroll
            for (int mi = 0; mi < 4; mi++)
#pragma unroll
                for (int ni = 0; ni < 8; ni++)
                    mma_tf32(acc[mi][ni], af[mi], bf[ni]);
        }
    };

    // 3-deep prologue: chunks 0,1,2 in flight before first compute
    issue(0, 0);
    issue(1, 1);
    issue(2, 2);
    asm volatile("cp.async.wait_group 2;" ::: "memory");   // chunk 0 ready
    __syncthreads();

    compute(0);
    __syncthreads();                                       // stage 0 free
    issue(3, 0);
    asm volatile("cp.async.wait_group 2;" ::: "memory");   // chunk 1 ready
    __syncthreads();

    compute(1);
    asm volatile("cp.async.wait_group 1;" ::: "memory");   // chunk 2 ready
    __syncthreads();

    compute(2);
    asm volatile("cp.async.wait_group 0;" ::: "memory");   // chunk 3 ready
    __syncthreads();

    compute(0);                                            // chunk 3 in stage 0

    // direct store: tile (i, j), coalesced float2 from registers
    {
        size_t rbase = ((size_t)b * NN + i * 128 + wm * 64 + g) * NN +
                       (size_t)j * 128 + wn * 64 + 2 * t;
#pragma unroll
        for (int mi = 0; mi < 4; mi++) {
            size_t r0 = rbase + (size_t)(mi * 16) * NN;
#pragma unroll
            for (int ni = 0; ni < 8; ni++) {
                float2 v0 = make_float2(-acc[mi][ni][0], -acc[mi][ni][1]);
                float2 v1 = make_float2(-acc[mi][ni][2], -acc[mi][ni][3]);
                *(float2*)(out + r0 + ni * 8) = v0;
                *(float2*)(out + r0 + (size_t)8 * NN + ni * 8) = v1;
            }
        }
    }

    if (j > i) {
        __syncthreads();      // everyone done reading stage buffers
        // stage transposed tile into the (now free) buffers: [col][row]
        float* STGb = smem;
        const int cbase = wn * 64 + 2 * t;
        const int rb = wm * 64 + g;
#pragma unroll
        for (int mi = 0; mi < 4; mi++) {
            int r = rb + mi * 16;
#pragma unroll
            for (int ni = 0; ni < 8; ni++) {
                int c = cbase + ni * 8;
                STGb[c * LDT + r]           = -acc[mi][ni][0];
                STGb[(c + 1) * LDT + r]     = -acc[mi][ni][1];
                STGb[c * LDT + r + 8]       = -acc[mi][ni][2];
                STGb[(c + 1) * LDT + r + 8] = -acc[mi][ni][3];
            }
        }
        __syncthreads();
        // mirrored store: tile (j, i), coalesced
        size_t tbase = ((size_t)b * NN + (size_t)j * 128) * NN + (size_t)i * 128;
#pragma unroll
        for (int it = 0; it < 32; it++) {
            int idx = tid + it * 128;
            int c = idx >> 5, q4 = idx & 31;
            float4 v = *(float4*)&STGb[c * LDT + q4 * 4];
            *(float4*)(out + tbase + (size_t)c * NN + q4 * 4) = v;
        }
    }
}

// ---------------------------------------------------------------------------
extern "C" void kernel_launch(void* const* d_in, const int* in_sizes, int n_in,
                              void* d_out, int out_size) {
    const float* obs        = (const float*)d_in[0];
    const float* gen_number = (const float*)d_in[1];
    const float* W_gen      = (const float*)d_in[2];
    const float* b_gen      = (const float*)d_in[3];
    const float* W_act      = (const float*)d_in[4];
    const float* b_act      = (const float*)d_in[5];
    const float* W_v1       = (const float*)d_in[6];
    const float* b_v1       = (const float*)d_in[7];
    const float* W_v2       = (const float*)d_in[8];
    const float* b_v2       = (const float*)d_in[9];
    float* out = (float*)d_out;

    cudaFuncSetAttribute(hc_kernel, cudaFuncAttributeMaxDynamicSharedMemorySize,
                         HC_SMEM_BYTES);
    cudaFuncSetAttribute(actor_kernel, cudaFuncAttributeMaxDynamicSharedMemorySize,
                         ACT_SMEM_BYTES);

    hc_kernel<<<dim3(NN / 128, BB), 256, HC_SMEM_BYTES>>>(
        obs, gen_number, W_gen, b_gen, W_act, b_act, W_v1, b_v1, W_v2, b_v2);
    actor_kernel<<<dim3(528, BB), 128, ACT_SMEM_BYTES>>>(out, out_size);
}

// round 16
// speedup vs baseline: 1.1551x; 1.0240x over previous
#include <cuda_runtime.h>
#include <math.h>
#include <stdint.h>

#define BB 4
#define NN 4096
#define FF 512
#define HA 128
#define HV 32

// Scratch (device globals: no allocation allowed)
__device__ float g_hn[BB][NN][HA];    // normalized h, row-major, tf32-rounded (8 MB)
__device__ float g_part[BB][64];

// ---------------------------------------------------------------------------
__device__ __forceinline__ float tf32r(float x) {
    uint32_t o;
    asm("cvt.rna.tf32.f32 %0, %1;" : "=r"(o) : "f"(x));
    return __uint_as_float(o);
}

__device__ __forceinline__ uint32_t s2u(const void* p) {
    uint32_t a;
    asm("{ .reg .u64 t; cvta.to.shared.u64 t, %1; cvt.u32.u64 %0, t; }"
        : "=r"(a) : "l"(p));
    return a;
}

__device__ __forceinline__ void cp16(uint32_t dst, const float* src) {
    asm volatile("cp.async.cg.shared.global [%0], [%1], 16;"
                 :: "r"(dst), "l"(src));
}

__device__ __forceinline__ void mma_tf32(float* d, const uint32_t* a,
                                         const uint32_t* b) {
    asm volatile(
        "mma.sync.aligned.m16n8k8.row.col.f32.tf32.tf32.f32 "
        "{%0,%1,%2,%3}, {%4,%5,%6,%7}, {%8,%9}, {%0,%1,%2,%3};"
        : "+f"(d[0]), "+f"(d[1]), "+f"(d[2]), "+f"(d[3])
        : "r"(a[0]), "r"(a[1]), "r"(a[2]), "r"(a[3]), "r"(b[0]), "r"(b[1]));
}

// ---------------------------------------------------------------------------
// FUSED hc kernel v2: 64-row tiles, 128 threads, 2 CTAs/SM (256 CTAs = one
// full wave). Warp grid 2(m)x2(n): warp tile 32x64 — per-warp fragment code
// identical to the proven version. 3-stage cp.async pipeline.
// ---------------------------------------------------------------------------
#define STAGE_W 7936
#define AS_OFF 0             // As: [64][36]  = 2304
#define BS_OFF 2304          // Bs: [32][136] = 4352
#define WS_OFF 6656          // Ws: [32][40]  = 1280
#define REDO 23808           // [64][8]
#define RINVO 24320          // [64]
#define CREDO 24384          // [64]
#define CWO 24448            // [2]
#define HC_FLOATS 24450
#define HC_SMEM_BYTES (HC_FLOATS * 4)
// staging (epilogue): [64][132] = 8448 words, overlaps the stage region

__global__ __launch_bounds__(128, 2) void hc_kernel(const float* __restrict__ obs,
                                                    const float* __restrict__ gen_number,
                                                    const float* __restrict__ W_gen,
                                                    const float* __restrict__ b_gen,
                                                    const float* __restrict__ W_act,
                                                    const float* __restrict__ b_act,
                                                    const float* __restrict__ W_v1,
                                                    const float* __restrict__ b_v1,
                                                    const float* __restrict__ W_v2,
                                                    const float* __restrict__ b_v2) {
    extern __shared__ float sm[];
    const uint32_t smb = s2u(sm);

    const int b  = blockIdx.y;
    const int m0 = blockIdx.x * 64;
    const int tid = threadIdx.x;
    const int wid = tid >> 5;            // 0..3
    const int lane = tid & 31;
    const int g = lane >> 2;
    const int t = lane & 3;
    const int wm = wid >> 1;             // 0..1 (32 rows each)
    const int wn = wid & 1;              // 0..1 (64 cols each)

    const float* obs_b = obs + ((size_t)b * NN + m0) * FF;

    float acc[2][8][4];
    float accv[2][4][4];
#pragma unroll
    for (int mi = 0; mi < 2; mi++) {
#pragma unroll
        for (int ni = 0; ni < 8; ni++)
#pragma unroll
            for (int q = 0; q < 4; q++) acc[mi][ni][q] = 0.f;
#pragma unroll
        for (int ni = 0; ni < 4; ni++)
#pragma unroll
            for (int q = 0; q < 4; q++) accv[mi][ni][q] = 0.f;
    }

    // issue chunk ck (32 k-values) into stage s
    auto issue = [&](int ck, int s) {
        const int k0 = ck * 32;
        uint32_t as = smb + (uint32_t)((s * STAGE_W + AS_OFF) * 4);
        uint32_t bs = smb + (uint32_t)((s * STAGE_W + BS_OFF) * 4);
        uint32_t ws = smb + (uint32_t)((s * STAGE_W + WS_OFF) * 4);
#pragma unroll
        for (int i = 0; i < 4; i++) {          // obs: 64x32 = 512 f4
            int c = tid + i * 128;
            int row = c >> 3, kc = c & 7;
            cp16(as + (uint32_t)(row * 36 + kc * 4) * 4u,
                 obs_b + (size_t)row * FF + k0 + kc * 4);
        }
#pragma unroll
        for (int i = 0; i < 8; i++) {          // W_act: 32x128 = 1024 f4
            int c = tid + i * 128;
            int kk = c >> 5, cg = c & 31;
            cp16(bs + (uint32_t)(kk * 136 + cg * 4) * 4u,
                 W_act + (size_t)(k0 + kk) * HA + cg * 4);
        }
#pragma unroll
        for (int i = 0; i < 2; i++) {          // W_v1: 32x32 = 256 f4
            int c = tid + i * 128;
            int kk = c >> 3, cg = c & 7;
            cp16(ws + (uint32_t)(kk * 40 + cg * 4) * 4u,
                 W_v1 + (size_t)(k0 + kk) * HV + cg * 4);
        }
    };

    issue(0, 0);
    asm volatile("cp.async.commit_group;" ::: "memory");
    issue(1, 1);
    asm volatile("cp.async.commit_group;" ::: "memory");
    issue(2, 2);
    asm volatile("cp.async.commit_group;" ::: "memory");
    asm volatile("cp.async.wait_group 2;" ::: "memory");
    __syncthreads();

#pragma unroll 1
    for (int ck = 0; ck < 16; ck++) {
        const int s = ck % 3;
        const float* A  = sm + s * STAGE_W + AS_OFF + wm * 32 * 36;
        const float* Bm = sm + s * STAGE_W + BS_OFF + wn * 64;
        const float* Wc = sm + s * STAGE_W + WS_OFF;
#pragma unroll
        for (int ks = 0; ks < 4; ks++) {
            const int kk = ks * 8;
            uint32_t af[2][4];
#pragma unroll
            for (int mi = 0; mi < 2; mi++) {
                const float* ap = A + (mi * 16 + g) * 36 + kk + t;
                af[mi][0] = __float_as_uint(ap[0]);
                af[mi][1] = __float_as_uint(ap[8 * 36]);
                af[mi][2] = __float_as_uint(ap[4]);
                af[mi][3] = __float_as_uint(ap[8 * 36 + 4]);
            }
            uint32_t bf[8][2];
#pragma unroll
            for (int ni = 0; ni < 8; ni++) {
                const float* bp = Bm + (kk + t) * 136 + ni * 8 + g;
                bf[ni][0] = __float_as_uint(bp[0]);
                bf[ni][1] = __float_as_uint(bp[4 * 136]);
            }
#pragma unroll
            for (int mi = 0; mi < 2; mi++)
#pragma unroll
                for (int ni = 0; ni < 8; ni++)
                    mma_tf32(acc[mi][ni], af[mi], bf[ni]);
            if (wn == 0) {
                uint32_t bc[4][2];
#pragma unroll
                for (int ni = 0; ni < 4; ni++) {
                    const float* bp = Wc + (kk + t) * 40 + ni * 8 + g;
                    bc[ni][0] = __float_as_uint(bp[0]);
                    bc[ni][1] = __float_as_uint(bp[4 * 40]);
                }
#pragma unroll
                for (int mi = 0; mi < 2; mi++)
#pragma unroll
                    for (int ni = 0; ni < 4; ni++)
                        mma_tf32(accv[mi][ni], af[mi], bc[ni]);
            }
        }
        __syncthreads();
        if (ck + 3 < 16) issue(ck + 3, s);
        asm volatile("cp.async.commit_group;" ::: "memory");
        if (ck < 15) {
            asm volatile("cp.async.wait_group 2;" ::: "memory");
            __syncthreads();
        }
    }

    float gv;
    {
        float x = gen_number[b] * W_gen[0] + b_gen[0];
        gv = (x > 0.f) ? x : 0.01f * x;
    }

#pragma unroll
    for (int ni = 0; ni < 8; ni++) {
        int c0 = wn * 64 + ni * 8 + 2 * t;
        float a0 = fmaf(gv, W_act[(size_t)FF * HA + c0], b_act[c0]);
        float a1 = fmaf(gv, W_act[(size_t)FF * HA + c0 + 1], b_act[c0 + 1]);
#pragma unroll
        for (int mi = 0; mi < 2; mi++) {
            acc[mi][ni][0] += a0; acc[mi][ni][1] += a1;
            acc[mi][ni][2] += a0; acc[mi][ni][3] += a1;
        }
    }

    float* RED = sm + REDO;
#pragma unroll
    for (int mi = 0; mi < 2; mi++)
#pragma unroll
        for (int d = 0; d < 2; d++) {
            float s = 0.f;
#pragma unroll
            for (int ni = 0; ni < 8; ni++) {
                s = fmaf(acc[mi][ni][2 * d], acc[mi][ni][2 * d], s);
                s = fmaf(acc[mi][ni][2 * d + 1], acc[mi][ni][2 * d + 1], s);
            }
            int row = wm * 32 + mi * 16 + g + 8 * d;
            RED[row * 8 + wn * 4 + t] = s;
        }
    __syncthreads();
    float* RINV = sm + RINVO;
    if (tid < 64) {
        float s = 0.f;
#pragma unroll
        for (int x = 0; x < 8; x++) s += RED[tid * 8 + x];
        RINV[tid] = 1.f / fmaxf(sqrtf(s), 1e-8f);
    }
    __syncthreads();

    // normalize + tf32 round -> stage (overlaps stage region, safe after syncs)
    float* STG = sm;
#pragma unroll
    for (int mi = 0; mi < 2; mi++)
#pragma unroll
        for (int d = 0; d < 2; d++) {
            int row = wm * 32 + mi * 16 + g + 8 * d;
            float iv = RINV[row];
#pragma unroll
            for (int ni = 0; ni < 8; ni++) {
                int col = wn * 64 + ni * 8 + 2 * t;
                STG[row * 132 + col]     = tf32r(acc[mi][ni][2 * d] * iv);
                STG[row * 132 + col + 1] = tf32r(acc[mi][ni][2 * d + 1] * iv);
            }
        }

    float* CRED = sm + CREDO;
    if (wn == 0) {
#pragma unroll
        for (int mi = 0; mi < 2; mi++)
#pragma unroll
            for (int d = 0; d < 2; d++) {
                float cv = 0.f;
#pragma unroll
                for (int ni = 0; ni < 4; ni++) {
#pragma unroll
                    for (int j = 0; j < 2; j++) {
                        int cc = ni * 8 + 2 * t + j;
                        float hvv = accv[mi][ni][2 * d + j] +
                                    fmaf(gv, W_v1[(size_t)FF * HV + cc], b_v1[cc]);
                        hvv = fmaxf(hvv, 0.f);
                        cv = fmaf(hvv, W_v2[cc], cv);
                    }
                }
                cv += __shfl_xor_sync(0xffffffffu, cv, 1);
                cv += __shfl_xor_sync(0xffffffffu, cv, 2);
                if (t == 0) {
                    int row = wm * 32 + mi * 16 + g + 8 * d;
                    CRED[row] = cv + b_v2[0];
                }
            }
    }
    __syncthreads();

    // coalesced copy of staged hn to global: 64x128 = 2048 f4
#pragma unroll
    for (int i = 0; i < 16; i++) {
        int idx = tid + i * 128;
        int row = idx >> 5, c4 = idx & 31;
        float4 v = *(float4*)&STG[row * 132 + c4 * 4];
        *(float4*)&g_hn[b][m0 + row][c4 * 4] = v;
    }

    float* CW = sm + CWO;
    if (tid < 64) {
        float v = CRED[tid];
#pragma unroll
        for (int off = 16; off > 0; off >>= 1)
            v += __shfl_down_sync(0xffffffffu, v, off);
        if ((tid & 31) == 0) CW[tid >> 5] = v;
    }
    __syncthreads();
    if (tid == 0)
        g_part[b][blockIdx.x] = CW[0] + CW[1];
}

// ---------------------------------------------------------------------------
// Actor v9 (R13, proven 80us): 128 threads, warp grid 2x2, warp tile 64x64,
// 128x128 CTA tile, 3-stage cp.async, 2 CTAs/SM. Symmetric j>=i + staged
// mirror. Only change: finalize sums 64 g_part entries.
// ---------------------------------------------------------------------------
#define CBUF 4608
#define ACT_WORDS (6 * CBUF)             // 27648
#define ACT_SMEM_BYTES (ACT_WORDS * 4)   // 110592
#define LDT 132                          // mirror staging stride

__global__ __launch_bounds__(128, 2) void actor_kernel(float* __restrict__ out,
                                                       int out_size) {
    extern __shared__ float smem[];
    const uint32_t smb = s2u(smem);

    const int tid = threadIdx.x;
    const int wid = tid >> 5;            // 0..3
    const int lane = tid & 31;
    const int g = lane >> 2;
    const int t = lane & 3;
    const int wm = wid >> 1;             // 0..1
    const int wn = wid & 1;              // 0..1
    const int b = blockIdx.y;
    const int cid = blockIdx.x;

    // fold critic finalize into one CTA
    if (cid == 0 && b == 0 && tid < BB) {
        float s = 0.f;
#pragma unroll
        for (int k = 0; k < 64; k++) s += g_part[tid][k];
        out[(size_t)out_size - BB + tid] = s * (1.f / NN);
    }

    // decode cid -> (i, j), j >= i, 528 per batch
    int i = 0, j;
    {
        int c = cid, ch;
        while (c >= (ch = 32 - i)) { c -= ch; i++; }
        j = i + c;
    }

    const float* aSrc = &g_hn[b][i * 128][0];
    const float* bSrc = &g_hn[b][j * 128][0];

    // chunk loader: chunk ck (32 k-values) of A and B into stage s
    auto issue = [&](int ck, int s) {
        const int k0 = ck * 32;
        uint32_t as = smb + (uint32_t)(s * CBUF * 4);
        uint32_t bs = smb + (uint32_t)((3 + s) * CBUF * 4);
#pragma unroll
        for (int it = 0; it < 8; it++) {
            int c = tid + it * 128;
            int row = c >> 3, kc = c & 7;
            cp16(as + (uint32_t)(row * 36 + kc * 4) * 4u,
                 aSrc + (size_t)row * HA + k0 + kc * 4);
        }
#pragma unroll
        for (int it = 0; it < 8; it++) {
            int c = tid + it * 128;
            int row = c >> 3, kc = c & 7;
            cp16(bs + (uint32_t)(row * 36 + kc * 4) * 4u,
                 bSrc + (size_t)row * HA + k0 + kc * 4);
        }
        asm volatile("cp.async.commit_group;" ::: "memory");
    };

    float acc[4][8][4];
#pragma unroll
    for (int mi = 0; mi < 4; mi++)
#pragma unroll
        for (int ni = 0; ni < 8; ni++)
#pragma unroll
            for (int q = 0; q < 4; q++) acc[mi][ni][q] = 0.f;

    // compute one chunk from stage s: 64x64 warp tile, scalar-LDS fragments
    auto compute = [&](int s) {
        const float* A  = smem + s * CBUF + (wm * 64) * 36;
        const float* Bm = smem + (3 + s) * CBUF + (wn * 64) * 36;
#pragma unroll
        for (int ks = 0; ks < 4; ks++) {
            const int kk = ks * 8;
            uint32_t af[4][4];
#pragma unroll
            for (int mi = 0; mi < 4; mi++) {
                const float* ap = A + (mi * 16 + g) * 36 + kk + t;
                af[mi][0] = __float_as_uint(ap[0]);
                af[mi][1] = __float_as_uint(ap[8 * 36]);
                af[mi][2] = __float_as_uint(ap[4]);
                af[mi][3] = __float_as_uint(ap[8 * 36 + 4]);
            }
            uint32_t bf[8][2];
#pragma unroll
            for (int ni = 0; ni < 8; ni++) {
                const float* bp = Bm + (ni * 8 + g) * 36 + kk + t;
                bf[ni][0] = __float_as_uint(bp[0]);
                bf[ni][1] = __float_as_uint(bp[4]);
            }
#pragma unroll
            for (int mi = 0; mi < 4; mi++)
#pragma unroll
                for (int ni = 0; ni < 8; ni++)
                    mma_tf32(acc[mi][ni], af[mi], bf[ni]);
        }
    };

    // 3-deep prologue: chunks 0,1,2 in flight before first compute
    issue(0, 0);
    issue(1, 1);
    issue(2, 2);
    asm volatile("cp.async.wait_group 2;" ::: "memory");   // chunk 0 ready
    __syncthreads();

    compute(0);
    __syncthreads();                                       // stage 0 free
    issue(3, 0);
    asm volatile("cp.async.wait_group 2;" ::: "memory");   // chunk 1 ready
    __syncthreads();

    compute(1);
    asm volatile("cp.async.wait_group 1;" ::: "memory");   // chunk 2 ready
    __syncthreads();

    compute(2);
    asm volatile("cp.async.wait_group 0;" ::: "memory");   // chunk 3 ready
    __syncthreads();

    compute(0);                                            // chunk 3 in stage 0

    // direct store: tile (i, j), coalesced float2 from registers
    {
        size_t rbase = ((size_t)b * NN + i * 128 + wm * 64 + g) * NN +
                       (size_t)j * 128 + wn * 64 + 2 * t;
#pragma unroll
        for (int mi = 0; mi < 4; mi++) {
            size_t r0 = rbase + (size_t)(mi * 16) * NN;
#pragma unroll
            for (int ni = 0; ni < 8; ni++) {
                float2 v0 = make_float2(-acc[mi][ni][0], -acc[mi][ni][1]);
                float2 v1 = make_float2(-acc[mi][ni][2], -acc[mi][ni][3]);
                *(float2*)(out + r0 + ni * 8) = v0;
                *(float2*)(out + r0 + (size_t)8 * NN + ni * 8) = v1;
            }
        }
    }

    if (j > i) {
        __syncthreads();      // everyone done reading stage buffers
        // stage transposed tile into the (now free) buffers: [col][row]
        float* STGb = smem;
        const int cbase = wn * 64 + 2 * t;
        const int rb = wm * 64 + g;
#pragma unroll
        for (int mi = 0; mi < 4; mi++) {
            int r = rb + mi * 16;
#pragma unroll
            for (int ni = 0; ni < 8; ni++) {
                int c = cbase + ni * 8;
                STGb[c * LDT + r]           = -acc[mi][ni][0];
                STGb[(c + 1) * LDT + r]     = -acc[mi][ni][1];
                STGb[c * LDT + r + 8]       = -acc[mi][ni][2];
                STGb[(c + 1) * LDT + r + 8] = -acc[mi][ni][3];
            }
        }
        __syncthreads();
        // mirrored store: tile (j, i), coalesced
        size_t tbase = ((size_t)b * NN + (size_t)j * 128) * NN + (size_t)i * 128;
#pragma unroll
        for (int it = 0; it < 32; it++) {
            int idx = tid + it * 128;
            int c = idx >> 5, q4 = idx & 31;
            float4 v = *(float4*)&STGb[c * LDT + q4 * 4];
            *(float4*)(out + tbase + (size_t)c * NN + q4 * 4) = v;
        }
    }
}

// ---------------------------------------------------------------------------
extern "C" void kernel_launch(void* const* d_in, const int* in_sizes, int n_in,
                              void* d_out, int out_size) {
    const float* obs        = (const float*)d_in[0];
    const float* gen_number = (const float*)d_in[1];
    const float* W_gen      = (const float*)d_in[2];
    const float* b_gen      = (const float*)d_in[3];
    const float* W_act      = (const float*)d_in[4];
    const float* b_act      = (const float*)d_in[5];
    const float* W_v1       = (const float*)d_in[6];
    const float* b_v1       = (const float*)d_in[7];
    const float* W_v2       = (const float*)d_in[8];
    const float* b_v2       = (const float*)d_in[9];
    float* out = (float*)d_out;

    cudaFuncSetAttribute(hc_kernel, cudaFuncAttributeMaxDynamicSharedMemorySize,
                         HC_SMEM_BYTES);
    cudaFuncSetAttribute(actor_kernel, cudaFuncAttributeMaxDynamicSharedMemorySize,
                         ACT_SMEM_BYTES);

    hc_kernel<<<dim3(NN / 64, BB), 128, HC_SMEM_BYTES>>>(
        obs, gen_number, W_gen, b_gen, W_act, b_act, W_v1, b_v1, W_v2, b_v2);
    actor_kernel<<<dim3(528, BB), 128, ACT_SMEM_BYTES>>>(out, out_size);
}